// round 1
// baseline (speedup 1.0000x reference)
#include <cuda_runtime.h>

// Problem: cosine self-attention
//   x: [16, 2048, 512] f32, out = softmax( (x x^T) / (|x_i||x_j|) ) @ x
// Scores are cosines => bounded by 1 => use fixed softmax shift exp(s-1):
// no online max tracking, single-pass flash accumulation.

#define BATCH   16
#define SEQ     2048
#define DIM     512
#define D4      (DIM/4)      // 128 float4 per row
#define BM      32
#define BN      32
#define NTHREADS 256
#define STRIDE4 129          // padded float4 row stride (bank-conflict-free)

__device__ float g_invnorm[BATCH * SEQ];

// ---------------- packed f32x2 helpers (sm_103a) ----------------
__device__ __forceinline__ unsigned long long fma2(unsigned long long a,
                                                   unsigned long long b,
                                                   unsigned long long c) {
    unsigned long long d;
    asm("fma.rn.f32x2 %0, %1, %2, %3;" : "=l"(d) : "l"(a), "l"(b), "l"(c));
    return d;
}
__device__ __forceinline__ unsigned long long mul2(unsigned long long a,
                                                   unsigned long long b) {
    unsigned long long d;
    asm("mul.rn.f32x2 %0, %1, %2;" : "=l"(d) : "l"(a), "l"(b));
    return d;
}
__device__ __forceinline__ unsigned long long dup2(float v) {
    unsigned long long r;
    asm("mov.b64 %0, {%1, %2};" : "=l"(r) : "f"(v), "f"(v));
    return r;
}
__device__ __forceinline__ float sum2(unsigned long long a) {
    float lo, hi;
    asm("mov.b64 {%0, %1}, %2;" : "=f"(lo), "=f"(hi) : "l"(a));
    return lo + hi;
}

union F4U {
    float4 f4;
    unsigned long long u[2];
};

// ---------------- kernel 1: row inverse L2 norms ----------------
// one warp per row; 8 warps per block
__global__ void rownorm_kernel(const float* __restrict__ x) {
    int row  = blockIdx.x * 8 + (threadIdx.x >> 5);
    int lane = threadIdx.x & 31;
    const float4* x4 = (const float4*)x + (size_t)row * D4;
    float ss = 0.f;
#pragma unroll
    for (int k = 0; k < 4; k++) {
        float4 v = x4[k * 32 + lane];
        ss += v.x * v.x + v.y * v.y + v.z * v.z + v.w * v.w;
    }
#pragma unroll
    for (int m = 16; m; m >>= 1) ss += __shfl_xor_sync(0xffffffffu, ss, m);
    if (lane == 0) g_invnorm[row] = 1.0f / sqrtf(ss);
}

// ---------------- kernel 2: fused flash cosine-attention ----------------
// grid: (SEQ/BM, BATCH), 256 threads.
// Warp w owns query rows qi = w*4 + (lane>>3).
// S phase : lane = ql*8 + kjg, thread computes s(qi, kj) for kj = 8*j + kjg
// PV phase: lane = ql*8 + dg,  thread owns float4 columns c = i*8 + dg (i=0..15)
__global__ __launch_bounds__(NTHREADS, 1)
void attn_kernel(const float* __restrict__ x, float* __restrict__ out) {
    extern __shared__ char smem_raw[];
    float4* sQ = (float4*)smem_raw;                         // BM*STRIDE4
    float4* sK = sQ + BM * STRIDE4;                         // BN*STRIDE4
    float*  sP = (float*)(sK + BN * STRIDE4);               // BM*33
    float*  sInvK = sP + BM * 33;                           // BN

    const int b     = blockIdx.y;
    const int qbase = blockIdx.x * BM;
    const int tid   = threadIdx.x;
    const int w     = tid >> 5;
    const int lane  = tid & 31;
    const int ql    = lane >> 3;   // 0..3
    const int kjg   = lane & 7;    // 0..7 (S phase)
    const int dg    = lane & 7;    // 0..7 (PV phase)
    const int qi    = w * 4 + ql;  // 0..31

    const float4* xb4  = (const float4*)x + (size_t)b * SEQ * D4;
    const float*  invn = g_invnorm + b * SEQ;

    // load Q tile, pre-scaled by invnorm_i
    for (int i = tid; i < BM * D4; i += NTHREADS) {
        int r = i >> 7, c = i & 127;
        float4 v = xb4[(size_t)(qbase + r) * D4 + c];
        float s = invn[qbase + r];
        v.x *= s; v.y *= s; v.z *= s; v.w *= s;
        sQ[r * STRIDE4 + c] = v;
    }

    // O accumulators: 16 float4 columns (c = i*8+dg) as 32 packed f32x2
    unsigned long long o2[32];
#pragma unroll
    for (int i = 0; i < 32; i++) o2[i] = 0ull;
    float l_acc = 0.f;

    for (int t = 0; t < SEQ / BN; t++) {
        __syncthreads();   // prior PV done reading sK/sP (also covers sQ at t=0)
        // load K tile (raw x rows) + key invnorms
        for (int i = tid; i < BN * D4; i += NTHREADS) {
            int r = i >> 7, c = i & 127;
            sK[r * STRIDE4 + c] = xb4[(size_t)(t * BN + r) * D4 + c];
        }
        if (tid < BN) sInvK[tid] = invn[t * BN + tid];
        __syncthreads();

        // ---- S phase: s(qi,kj) = <q_hat, x_kj> * invnorm_kj ----
        unsigned long long acc[8];
#pragma unroll
        for (int i = 0; i < 8; i++) acc[i] = 0ull;
        const float4* qrow = sQ + qi * STRIDE4;
#pragma unroll 4
        for (int c = 0; c < D4; c++) {
            F4U q; q.f4 = qrow[c];
#pragma unroll
            for (int j = 0; j < 4; j++) {
                F4U k; k.f4 = sK[(8 * j + kjg) * STRIDE4 + c];
                acc[2 * j]     = fma2(q.u[0], k.u[0], acc[2 * j]);
                acc[2 * j + 1] = fma2(q.u[1], k.u[1], acc[2 * j + 1]);
            }
        }
        float rowpart = 0.f;
#pragma unroll
        for (int j = 0; j < 4; j++) {
            int kj = 8 * j + kjg;
            float s = (sum2(acc[2 * j]) + sum2(acc[2 * j + 1])) * sInvK[kj];
            float p = __expf(s - 1.0f);   // cosine <= 1: fixed softmax shift
            sP[qi * 33 + kj] = p;
            rowpart += p;
        }
        // reduce row sum over the 8 lanes sharing qi (butterfly: all 8 get it)
        rowpart += __shfl_xor_sync(0xffffffffu, rowpart, 1);
        rowpart += __shfl_xor_sync(0xffffffffu, rowpart, 2);
        rowpart += __shfl_xor_sync(0xffffffffu, rowpart, 4);
        l_acc += rowpart;
        __syncthreads();

        // ---- PV phase: O(qi, :) += p * x_kj ----
#pragma unroll 4
        for (int kj = 0; kj < BN; kj++) {
            unsigned long long p2 = dup2(sP[qi * 33 + kj]);
            const float4* krow = sK + kj * STRIDE4;
#pragma unroll
            for (int i = 0; i < 16; i++) {
                F4U k; k.f4 = krow[i * 8 + dg];
                o2[2 * i]     = fma2(p2, k.u[0], o2[2 * i]);
                o2[2 * i + 1] = fma2(p2, k.u[1], o2[2 * i + 1]);
            }
        }
    }

    // normalize and write out (all 8 lanes of a qi-group hold the full l_acc)
    unsigned long long linv2 = dup2(1.0f / l_acc);
    float4* outb = (float4*)out + (size_t)b * SEQ * D4 + (size_t)(qbase + qi) * D4;
#pragma unroll
    for (int i = 0; i < 16; i++) {
        F4U v;
        v.u[0] = mul2(o2[2 * i],     linv2);
        v.u[1] = mul2(o2[2 * i + 1], linv2);
        outb[i * 8 + dg] = v.f4;
    }
}

// ---------------- launch ----------------
extern "C" void kernel_launch(void* const* d_in, const int* in_sizes, int n_in,
                              void* d_out, int out_size) {
    const float* x = (const float*)d_in[0];
    float* out = (float*)d_out;

    static const int SMEM_BYTES =
        (BM * STRIDE4 + BN * STRIDE4) * (int)sizeof(float4) +
        (BM * 33 + BN) * (int)sizeof(float);

    static bool configured = false;
    if (!configured) {
        cudaFuncSetAttribute(attn_kernel,
                             cudaFuncAttributeMaxDynamicSharedMemorySize,
                             SMEM_BYTES);
        configured = true;
    }

    rownorm_kernel<<<BATCH * SEQ / 8, NTHREADS>>>(x);
    attn_kernel<<<dim3(SEQ / BM, BATCH), NTHREADS, SMEM_BYTES>>>(x, out);
}

// round 2
// speedup vs baseline: 1.0524x; 1.0524x over previous
#include <cuda_runtime.h>

// Problem: cosine self-attention
//   x: [16, 2048, 512] f32, out = softmax( (x x^T) / (|x_i||x_j|) ) @ x
// Scores are cosines => bounded by 1 => use fixed softmax shift exp(s-1):
// no online max tracking, single-pass flash accumulation.

#define BATCH   16
#define SEQ     2048
#define DIM     512
#define D4      (DIM/4)      // 128 float4 per row
#define BM      32
#define BN      32
#define NTHREADS 256
#define STRIDE4 129          // padded float4 row stride (bank-conflict-free)

__device__ float g_invnorm[BATCH * SEQ];

// ---------------- packed f32x2 helpers (sm_103a) ----------------
__device__ __forceinline__ unsigned long long fma2(unsigned long long a,
                                                   unsigned long long b,
                                                   unsigned long long c) {
    unsigned long long d;
    asm("fma.rn.f32x2 %0, %1, %2, %3;" : "=l"(d) : "l"(a), "l"(b), "l"(c));
    return d;
}
__device__ __forceinline__ unsigned long long mul2(unsigned long long a,
                                                   unsigned long long b) {
    unsigned long long d;
    asm("mul.rn.f32x2 %0, %1, %2;" : "=l"(d) : "l"(a), "l"(b));
    return d;
}
__device__ __forceinline__ unsigned long long dup2(float v) {
    unsigned long long r;
    asm("mov.b64 %0, {%1, %2};" : "=l"(r) : "f"(v), "f"(v));
    return r;
}
__device__ __forceinline__ float sum2(unsigned long long a) {
    float lo, hi;
    asm("mov.b64 {%0, %1}, %2;" : "=f"(lo), "=f"(hi) : "l"(a));
    return lo + hi;
}

union F4U {
    float4 f4;
    unsigned long long u[2];
};

// ---------------- kernel 1: row inverse L2 norms ----------------
// one warp per row; 8 warps per block
__global__ void rownorm_kernel(const float* __restrict__ x) {
    int row  = blockIdx.x * 8 + (threadIdx.x >> 5);
    int lane = threadIdx.x & 31;
    const float4* x4 = (const float4*)x + (size_t)row * D4;
    float ss = 0.f;
#pragma unroll
    for (int k = 0; k < 4; k++) {
        float4 v = x4[k * 32 + lane];
        ss += v.x * v.x + v.y * v.y + v.z * v.z + v.w * v.w;
    }
#pragma unroll
    for (int m = 16; m; m >>= 1) ss += __shfl_xor_sync(0xffffffffu, ss, m);
    if (lane == 0) g_invnorm[row] = 1.0f / sqrtf(ss);
}

// ---------------- kernel 2: fused flash cosine-attention ----------------
// grid: (SEQ/BM, BATCH), 256 threads.
// Warp w owns query rows qi = w*4 + (lane>>3).
// S phase : lane = ql*8 + kjg, thread computes s(qi, kj) for kj = 8*j + kjg
// PV phase: lane = ql*8 + dg,  thread owns float4 columns c = i*8 + dg (i=0..15)
__global__ __launch_bounds__(NTHREADS, 1)
void attn_kernel(const float* __restrict__ x, float* __restrict__ out) {
    extern __shared__ char smem_raw[];
    float4* sQ = (float4*)smem_raw;                         // BM*STRIDE4
    float4* sK = sQ + BM * STRIDE4;                         // BN*STRIDE4
    float*  sP = (float*)(sK + BN * STRIDE4);               // BM*33
    float*  sInvK = sP + BM * 33;                           // BN

    const int b     = blockIdx.y;
    const int qbase = blockIdx.x * BM;
    const int tid   = threadIdx.x;
    const int w     = tid >> 5;
    const int lane  = tid & 31;
    const int ql    = lane >> 3;   // 0..3
    const int kjg   = lane & 7;    // 0..7 (S phase)
    const int dg    = lane & 7;    // 0..7 (PV phase)
    const int qi    = w * 4 + ql;  // 0..31

    const float4* xb4  = (const float4*)x + (size_t)b * SEQ * D4;
    const float*  invn = g_invnorm + b * SEQ;

    // load Q tile, pre-scaled by invnorm_i
    for (int i = tid; i < BM * D4; i += NTHREADS) {
        int r = i >> 7, c = i & 127;
        float4 v = xb4[(size_t)(qbase + r) * D4 + c];
        float s = invn[qbase + r];
        v.x *= s; v.y *= s; v.z *= s; v.w *= s;
        sQ[r * STRIDE4 + c] = v;
    }

    // O accumulators: 16 float4 columns (c = i*8+dg) as 32 packed f32x2
    unsigned long long o2[32];
#pragma unroll
    for (int i = 0; i < 32; i++) o2[i] = 0ull;
    float l_acc = 0.f;

    for (int t = 0; t < SEQ / BN; t++) {
        __syncthreads();   // prior PV done reading sK/sP (also covers sQ at t=0)
        // load K tile (raw x rows) + key invnorms
        for (int i = tid; i < BN * D4; i += NTHREADS) {
            int r = i >> 7, c = i & 127;
            sK[r * STRIDE4 + c] = xb4[(size_t)(t * BN + r) * D4 + c];
        }
        if (tid < BN) sInvK[tid] = invn[t * BN + tid];
        __syncthreads();

        // ---- S phase: s(qi,kj) = <q_hat, x_kj> * invnorm_kj ----
        unsigned long long acc[8];
#pragma unroll
        for (int i = 0; i < 8; i++) acc[i] = 0ull;
        const float4* qrow = sQ + qi * STRIDE4;
#pragma unroll 4
        for (int c = 0; c < D4; c++) {
            F4U q; q.f4 = qrow[c];
#pragma unroll
            for (int j = 0; j < 4; j++) {
                F4U k; k.f4 = sK[(8 * j + kjg) * STRIDE4 + c];
                acc[2 * j]     = fma2(q.u[0], k.u[0], acc[2 * j]);
                acc[2 * j + 1] = fma2(q.u[1], k.u[1], acc[2 * j + 1]);
            }
        }
        float rowpart = 0.f;
#pragma unroll
        for (int j = 0; j < 4; j++) {
            int kj = 8 * j + kjg;
            float s = (sum2(acc[2 * j]) + sum2(acc[2 * j + 1])) * sInvK[kj];
            float p = __expf(s - 1.0f);   // cosine <= 1: fixed softmax shift
            sP[qi * 33 + kj] = p;
            rowpart += p;
        }
        // reduce row sum over the 8 lanes sharing qi (butterfly: all 8 get it)
        rowpart += __shfl_xor_sync(0xffffffffu, rowpart, 1);
        rowpart += __shfl_xor_sync(0xffffffffu, rowpart, 2);
        rowpart += __shfl_xor_sync(0xffffffffu, rowpart, 4);
        l_acc += rowpart;
        __syncthreads();

        // ---- PV phase: O(qi, :) += p * x_kj ----
#pragma unroll 4
        for (int kj = 0; kj < BN; kj++) {
            unsigned long long p2 = dup2(sP[qi * 33 + kj]);
            const float4* krow = sK + kj * STRIDE4;
#pragma unroll
            for (int i = 0; i < 16; i++) {
                F4U k; k.f4 = krow[i * 8 + dg];
                o2[2 * i]     = fma2(p2, k.u[0], o2[2 * i]);
                o2[2 * i + 1] = fma2(p2, k.u[1], o2[2 * i + 1]);
            }
        }
    }

    // normalize and write out (all 8 lanes of a qi-group hold the full l_acc)
    unsigned long long linv2 = dup2(1.0f / l_acc);
    float4* outb = (float4*)out + (size_t)b * SEQ * D4 + (size_t)(qbase + qi) * D4;
#pragma unroll
    for (int i = 0; i < 16; i++) {
        F4U v;
        v.u[0] = mul2(o2[2 * i],     linv2);
        v.u[1] = mul2(o2[2 * i + 1], linv2);
        outb[i * 8 + dg] = v.f4;
    }
}

// ---------------- launch ----------------
extern "C" void kernel_launch(void* const* d_in, const int* in_sizes, int n_in,
                              void* d_out, int out_size) {
    const float* x = (const float*)d_in[0];
    float* out = (float*)d_out;

    static const int SMEM_BYTES =
        (BM * STRIDE4 + BN * STRIDE4) * (int)sizeof(float4) +
        (BM * 33 + BN) * (int)sizeof(float);

    static bool configured = false;
    if (!configured) {
        cudaFuncSetAttribute(attn_kernel,
                             cudaFuncAttributeMaxDynamicSharedMemorySize,
                             SMEM_BYTES);
        configured = true;
    }

    rownorm_kernel<<<BATCH * SEQ / 8, NTHREADS>>>(x);
    attn_kernel<<<dim3(SEQ / BM, BATCH), NTHREADS, SMEM_BYTES>>>(x, out);
}

// round 3
// speedup vs baseline: 3.0112x; 2.8613x over previous
#include <cuda_runtime.h>

// Cosine self-attention, unfused:
//   xhat = x / |x|                (kernel 1)
//   P    = exp(xhat @ xhat^T - 1) (kernel 2, SGEMM 128x128x8 + exp epilogue)
//   rinv = 1 / rowsum(P)          (kernel 3)
//   out  = (P @ x) * rinv         (kernel 4, SGEMM 128x128x8)
// Scores are cosines (<=1) so the fixed shift exp(s-1) is a valid softmax
// shift (cancels in the ratio).

#define BATCH 16
#define SEQ   2048
#define DIM   512
#define NT    256

__device__ float g_xhat[BATCH * SEQ * DIM];          // 64 MB
__device__ float g_P[BATCH * SEQ * SEQ];             // 256 MB scratch
__device__ float g_rinv[BATCH * SEQ];

// ---------------- packed f32x2 helpers (sm_103a) ----------------
__device__ __forceinline__ unsigned long long fma2(unsigned long long a,
                                                   unsigned long long b,
                                                   unsigned long long c) {
    unsigned long long d;
    asm("fma.rn.f32x2 %0, %1, %2, %3;" : "=l"(d) : "l"(a), "l"(b), "l"(c));
    return d;
}
__device__ __forceinline__ unsigned long long mul2(unsigned long long a,
                                                   unsigned long long b) {
    unsigned long long d;
    asm("mul.rn.f32x2 %0, %1, %2;" : "=l"(d) : "l"(a), "l"(b));
    return d;
}
__device__ __forceinline__ unsigned long long dup2(float v) {
    unsigned long long r;
    asm("mov.b64 %0, {%1, %2};" : "=l"(r) : "f"(v), "f"(v));
    return r;
}
__device__ __forceinline__ void unpack2(unsigned long long a, float& lo, float& hi) {
    asm("mov.b64 {%0, %1}, %2;" : "=f"(lo), "=f"(hi) : "l"(a));
}

union F4U {
    float4 f4;
    unsigned long long u[2];
    float f[4];
};

// ---------------- kernel 1: xhat = x * (1/|x|) ----------------
// one warp per row, row kept in registers
__global__ void xhat_kernel(const float* __restrict__ x) {
    int row  = blockIdx.x * 8 + (threadIdx.x >> 5);
    int lane = threadIdx.x & 31;
    const float4* xr = (const float4*)x + (size_t)row * (DIM / 4);
    float4 v[4];
    float ss = 0.f;
#pragma unroll
    for (int i = 0; i < 4; i++) {
        v[i] = xr[i * 32 + lane];
        ss += v[i].x * v[i].x + v[i].y * v[i].y + v[i].z * v[i].z + v[i].w * v[i].w;
    }
#pragma unroll
    for (int m = 16; m; m >>= 1) ss += __shfl_xor_sync(0xffffffffu, ss, m);
    float s = 1.0f / sqrtf(ss);
    float4* o = (float4*)g_xhat + (size_t)row * (DIM / 4);
#pragma unroll
    for (int i = 0; i < 4; i++) {
        float4 w = v[i];
        w.x *= s; w.y *= s; w.z *= s; w.w *= s;
        o[i * 32 + lane] = w;
    }
}

// ---------------- kernel 2: P = exp(xhat @ xhat^T - 1) ----------------
// 128x128x8 SGEMM tile, 256 threads, 8x8 per thread, f32x2 FMAs,
// double-buffered smem.
__global__ __launch_bounds__(NT, 2) void gemm1_kernel() {
    __shared__ float As[2][8][128];
    __shared__ float Bs[2][8][128];

    const int b  = blockIdx.z;
    const int m0 = blockIdx.y * 128;
    const int n0 = blockIdx.x * 128;
    const int tid = threadIdx.x;
    const int tx = tid & 15;       // 16 col-groups of 8
    const int ty = tid >> 4;       // 16 row-groups of 8

    const float* Xb = g_xhat + (size_t)b * SEQ * DIM;
    const int lrow = tid >> 1;           // 0..127
    const int lk4  = (tid & 1) * 4;      // 0 or 4
    const float4* Ag = (const float4*)(Xb + (size_t)(m0 + lrow) * DIM);
    const float4* Bg = (const float4*)(Xb + (size_t)(n0 + lrow) * DIM);

    unsigned long long c2[8][4];
#pragma unroll
    for (int i = 0; i < 8; i++)
#pragma unroll
        for (int j = 0; j < 4; j++) c2[i][j] = 0ull;

    // preload tile 0
    {
        F4U av, bv;
        av.f4 = Ag[lk4 >> 2];
        bv.f4 = Bg[lk4 >> 2];
#pragma unroll
        for (int j = 0; j < 4; j++) {
            As[0][lk4 + j][lrow] = av.f[j];
            Bs[0][lk4 + j][lrow] = bv.f[j];
        }
    }
    __syncthreads();

    const int T = DIM / 8;  // 64
    for (int t = 0; t < T; t++) {
        const int buf = t & 1;
        F4U av, bv;
        if (t + 1 < T) {
            int kidx = ((t + 1) * 8 + lk4) >> 2;
            av.f4 = Ag[kidx];
            bv.f4 = Bg[kidx];
        }
#pragma unroll
        for (int k = 0; k < 8; k++) {
            F4U a0, a1, b0, b1;
            a0.f4 = *(const float4*)&As[buf][k][ty * 8];
            a1.f4 = *(const float4*)&As[buf][k][ty * 8 + 4];
            b0.f4 = *(const float4*)&Bs[buf][k][tx * 8];
            b1.f4 = *(const float4*)&Bs[buf][k][tx * 8 + 4];
            unsigned long long ad[8];
            ad[0] = dup2(a0.f[0]); ad[1] = dup2(a0.f[1]);
            ad[2] = dup2(a0.f[2]); ad[3] = dup2(a0.f[3]);
            ad[4] = dup2(a1.f[0]); ad[5] = dup2(a1.f[1]);
            ad[6] = dup2(a1.f[2]); ad[7] = dup2(a1.f[3]);
            unsigned long long bp[4] = {b0.u[0], b0.u[1], b1.u[0], b1.u[1]};
#pragma unroll
            for (int i = 0; i < 8; i++)
#pragma unroll
                for (int j = 0; j < 4; j++)
                    c2[i][j] = fma2(ad[i], bp[j], c2[i][j]);
        }
        if (t + 1 < T) {
            int nxt = buf ^ 1;
#pragma unroll
            for (int j = 0; j < 4; j++) {
                As[nxt][lk4 + j][lrow] = av.f[j];
                Bs[nxt][lk4 + j][lrow] = bv.f[j];
            }
            __syncthreads();
        }
    }

    // epilogue: p = exp(s - 1), write 8x8
#pragma unroll
    for (int i = 0; i < 8; i++) {
        float* pr = g_P + ((size_t)b * SEQ + m0 + ty * 8 + i) * SEQ + n0;
        F4U w0, w1;
        float lo, hi;
        unpack2(c2[i][0], lo, hi);
        w0.f[0] = __expf(lo - 1.0f); w0.f[1] = __expf(hi - 1.0f);
        unpack2(c2[i][1], lo, hi);
        w0.f[2] = __expf(lo - 1.0f); w0.f[3] = __expf(hi - 1.0f);
        unpack2(c2[i][2], lo, hi);
        w1.f[0] = __expf(lo - 1.0f); w1.f[1] = __expf(hi - 1.0f);
        unpack2(c2[i][3], lo, hi);
        w1.f[2] = __expf(lo - 1.0f); w1.f[3] = __expf(hi - 1.0f);
        ((float4*)pr)[2 * tx]     = w0.f4;
        ((float4*)pr)[2 * tx + 1] = w1.f4;
    }
}

// ---------------- kernel 3: rinv = 1 / rowsum(P) ----------------
// one warp per row
__global__ void rowsum_kernel() {
    int row  = blockIdx.x * 8 + (threadIdx.x >> 5);
    int lane = threadIdx.x & 31;
    const float4* p = (const float4*)(g_P + (size_t)row * SEQ);
    float s = 0.f;
#pragma unroll
    for (int i = 0; i < 16; i++) {
        float4 v = p[i * 32 + lane];
        s += v.x + v.y + v.z + v.w;
    }
#pragma unroll
    for (int m = 16; m; m >>= 1) s += __shfl_xor_sync(0xffffffffu, s, m);
    if (lane == 0) g_rinv[row] = 1.0f / s;
}

// ---------------- kernel 4: out = (P @ x) * rinv ----------------
__global__ __launch_bounds__(NT, 2) void gemm2_kernel(const float* __restrict__ x,
                                                      float* __restrict__ out) {
    __shared__ float As[2][8][128];
    __shared__ float Bs[2][8][128];

    const int b  = blockIdx.z;
    const int m0 = blockIdx.y * 128;
    const int n0 = blockIdx.x * 128;
    const int tid = threadIdx.x;
    const int tx = tid & 15;
    const int ty = tid >> 4;

    // A: P rows (transpose-load). B: x rows (direct).
    const int lrow = tid >> 1;
    const int lk4  = (tid & 1) * 4;
    const float4* Ag = (const float4*)(g_P + ((size_t)b * SEQ + m0 + lrow) * SEQ);
    const int bk = tid >> 5;             // 0..7
    const int bj = (tid & 31) * 4;       // 0..124
    const float* Xb = x + (size_t)b * SEQ * DIM;

    unsigned long long c2[8][4];
#pragma unroll
    for (int i = 0; i < 8; i++)
#pragma unroll
        for (int j = 0; j < 4; j++) c2[i][j] = 0ull;

    // preload tile 0
    {
        F4U av;
        av.f4 = Ag[lk4 >> 2];
#pragma unroll
        for (int j = 0; j < 4; j++) As[0][lk4 + j][lrow] = av.f[j];
        float4 bv = *(const float4*)(Xb + (size_t)bk * DIM + n0 + bj);
        *(float4*)&Bs[0][bk][bj] = bv;
    }
    __syncthreads();

    const int T = SEQ / 8;  // 256
    for (int t = 0; t < T; t++) {
        const int buf = t & 1;
        F4U av;
        float4 bv;
        if (t + 1 < T) {
            av.f4 = Ag[((t + 1) * 8 + lk4) >> 2];
            bv = *(const float4*)(Xb + (size_t)((t + 1) * 8 + bk) * DIM + n0 + bj);
        }
#pragma unroll
        for (int k = 0; k < 8; k++) {
            F4U a0, a1, b0, b1;
            a0.f4 = *(const float4*)&As[buf][k][ty * 8];
            a1.f4 = *(const float4*)&As[buf][k][ty * 8 + 4];
            b0.f4 = *(const float4*)&Bs[buf][k][tx * 8];
            b1.f4 = *(const float4*)&Bs[buf][k][tx * 8 + 4];
            unsigned long long ad[8];
            ad[0] = dup2(a0.f[0]); ad[1] = dup2(a0.f[1]);
            ad[2] = dup2(a0.f[2]); ad[3] = dup2(a0.f[3]);
            ad[4] = dup2(a1.f[0]); ad[5] = dup2(a1.f[1]);
            ad[6] = dup2(a1.f[2]); ad[7] = dup2(a1.f[3]);
            unsigned long long bp[4] = {b0.u[0], b0.u[1], b1.u[0], b1.u[1]};
#pragma unroll
            for (int i = 0; i < 8; i++)
#pragma unroll
                for (int j = 0; j < 4; j++)
                    c2[i][j] = fma2(ad[i], bp[j], c2[i][j]);
        }
        if (t + 1 < T) {
            int nxt = buf ^ 1;
#pragma unroll
            for (int j = 0; j < 4; j++) As[nxt][lk4 + j][lrow] = av.f[j];
            *(float4*)&Bs[nxt][bk][bj] = bv;
            __syncthreads();
        }
    }

    // epilogue: multiply by rinv, write
#pragma unroll
    for (int i = 0; i < 8; i++) {
        unsigned long long r2 = dup2(g_rinv[b * SEQ + m0 + ty * 8 + i]);
        float* orow = out + ((size_t)b * SEQ + m0 + ty * 8 + i) * DIM + n0;
        F4U w0, w1;
        w0.u[0] = mul2(c2[i][0], r2);
        w0.u[1] = mul2(c2[i][1], r2);
        w1.u[0] = mul2(c2[i][2], r2);
        w1.u[1] = mul2(c2[i][3], r2);
        ((float4*)orow)[2 * tx]     = w0.f4;
        ((float4*)orow)[2 * tx + 1] = w1.f4;
    }
}

// ---------------- launch ----------------
extern "C" void kernel_launch(void* const* d_in, const int* in_sizes, int n_in,
                              void* d_out, int out_size) {
    const float* x = (const float*)d_in[0];
    float* out = (float*)d_out;

    xhat_kernel<<<BATCH * SEQ / 8, NT>>>(x);
    gemm1_kernel<<<dim3(SEQ / 128, SEQ / 128, BATCH), NT>>>();
    rowsum_kernel<<<BATCH * SEQ / 8, NT>>>();
    gemm2_kernel<<<dim3(DIM / 128, SEQ / 128, BATCH), NT>>>(x, out);
}

// round 5
// speedup vs baseline: 5.0496x; 1.6769x over previous
#include <cuda_runtime.h>
#include <cstdint>

// Cosine self-attention via legacy tensor-core tf32 mma.sync (sm_80 baseline PTX,
// works under the harness's compute_103 virtual arch; tcgen05 is 'a'-gated and
// rejected by ptxas here).
//   xhat = x / |x|
//   xT   = per-batch transpose of x     (B operand for GEMM2, K-major)
//   P    = exp(xhat @ xhat^T - 1)       (tf32 mma.sync, 128x128 CTA tiles)
//   rinv = 1 / rowsum(P)
//   out  = (P @ x) * rinv               (tf32 mma.sync)
// cosine <= 1 => fixed softmax shift exp(s-1) cancels in the ratio.

#define BATCH 16
#define SEQ   2048
#define DIM   512
#define CK    16                       // K per chunk (2 mma k-steps of 8)

__device__ float g_xhat[BATCH * SEQ * DIM];        // 64 MB
__device__ float g_xT[BATCH * DIM * SEQ];          // 64 MB
__device__ float g_P[(size_t)BATCH * SEQ * SEQ];   // 256 MB
__device__ float g_rinv[BATCH * SEQ];

// ---------------- helpers ----------------
__device__ __forceinline__ uint32_t f2tf32(float x) {
    uint32_t r;
    asm("cvt.rna.tf32.f32 %0, %1;" : "=r"(r) : "f"(x));
    return r;
}
__device__ __forceinline__ void mma8(float c[4], const uint32_t a[4],
                                     const uint32_t b[2]) {
    asm volatile(
        "mma.sync.aligned.m16n8k8.row.col.f32.tf32.tf32.f32 "
        "{%0,%1,%2,%3}, {%4,%5,%6,%7}, {%8,%9}, {%0,%1,%2,%3};"
        : "+f"(c[0]), "+f"(c[1]), "+f"(c[2]), "+f"(c[3])
        : "r"(a[0]), "r"(a[1]), "r"(a[2]), "r"(a[3]), "r"(b[0]), "r"(b[1]));
}

// ---------------- kernel: xhat ----------------
__global__ void xhat_kernel(const float* __restrict__ x) {
    int row  = blockIdx.x * 8 + (threadIdx.x >> 5);
    int lane = threadIdx.x & 31;
    const float4* xr = (const float4*)x + (size_t)row * (DIM / 4);
    float4 v[4];
    float ss = 0.f;
#pragma unroll
    for (int i = 0; i < 4; i++) {
        v[i] = xr[i * 32 + lane];
        ss += v[i].x * v[i].x + v[i].y * v[i].y + v[i].z * v[i].z + v[i].w * v[i].w;
    }
#pragma unroll
    for (int m = 16; m; m >>= 1) ss += __shfl_xor_sync(0xffffffffu, ss, m);
    float s = 1.0f / sqrtf(ss);
    float4* o = (float4*)g_xhat + (size_t)row * (DIM / 4);
#pragma unroll
    for (int i = 0; i < 4; i++) {
        float4 w = v[i];
        w.x *= s; w.y *= s; w.z *= s; w.w *= s;
        o[i * 32 + lane] = w;
    }
}

// ---------------- kernel: xT (per-batch transpose) ----------------
__global__ void xT_kernel(const float* __restrict__ x) {
    __shared__ float t[32][33];
    const int b = blockIdx.z, s0 = blockIdx.x * 32, d0 = blockIdx.y * 32;
    const int tx = threadIdx.x, ty = threadIdx.y;
#pragma unroll
    for (int i = 0; i < 4; i++)
        t[ty + 8 * i][tx] = x[((size_t)b * SEQ + s0 + ty + 8 * i) * DIM + d0 + tx];
    __syncthreads();
#pragma unroll
    for (int i = 0; i < 4; i++)
        g_xT[((size_t)b * DIM + d0 + ty + 8 * i) * SEQ + s0 + tx] = t[tx][ty + 8 * i];
}

// ---------------- GEMM core (128x128 CTA, 4 warps, 64x64 warp tiles) ----------
// Fragment-ordered smem staging:
//   A: offset = (kstep*8  + mtile)*128 + reg*32 + (grp*4 + c)
//   B: offset = (kstep*16 + ntile)*64  + reg*32 + (grp*4 + c)
// STS.128 conflict-free (phases hit 8 consecutive float4s); frag LDS.32
// lane-stride-1 conflict-free.
#define ACHUNK 2048   // 128 rows * 16 k
#define BCHUNK 2048

__device__ __forceinline__ void ldg_stage(const float4* Ag, const float4* Bg,
                                          int t, uint4 sa[4], uint4 sb[4]) {
#pragma unroll
    for (int q = 0; q < 4; q++) {
        float4 v = Ag[t * 4 + q];
        sa[q].x = f2tf32(v.x); sa[q].y = f2tf32(v.y);
        sa[q].z = f2tf32(v.z); sa[q].w = f2tf32(v.w);
        float4 w = Bg[t * 4 + q];
        sb[q].x = f2tf32(w.x); sb[q].y = f2tf32(w.y);
        sb[q].z = f2tf32(w.z); sb[q].w = f2tf32(w.w);
    }
}

__device__ __forceinline__ void sts_stage(float* Abuf, float* Bbuf,
                                          const uint4 sa[4], const uint4 sb[4],
                                          int tid) {
    const int r = tid;
    const int mtile = r >> 4, ntile = r >> 3, grp = r & 7, rb = (r >> 3) & 1;
#pragma unroll
    for (int q = 0; q < 4; q++) {
        int blkA = (q >> 1) * 8 + mtile;
        int regA = (q & 1) * 2 + rb;
        *(uint4*)&Abuf[blkA * 128 + regA * 32 + grp * 4] = sa[q];
        int blkB = (q >> 1) * 16 + ntile;
        int regB = (q & 1);
        *(uint4*)&Bbuf[blkB * 64 + regB * 32 + grp * 4] = sb[q];
    }
}

__device__ __forceinline__ void compute_chunk(const float* Abuf, const float* Bbuf,
                                              float c[4][8][4], int wm, int wn,
                                              int lane) {
#pragma unroll
    for (int ks = 0; ks < 2; ks++) {
        uint32_t a[4][4], b[8][2];
#pragma unroll
        for (int mt = 0; mt < 4; mt++) {
            const float* p = Abuf + (ks * 8 + wm * 4 + mt) * 128 + lane;
#pragma unroll
            for (int j = 0; j < 4; j++)
                a[mt][j] = __float_as_uint(p[j * 32]);
        }
#pragma unroll
        for (int nt = 0; nt < 8; nt++) {
            const float* p = Bbuf + (ks * 16 + wn * 8 + nt) * 64 + lane;
#pragma unroll
            for (int j = 0; j < 2; j++)
                b[nt][j] = __float_as_uint(p[j * 32]);
        }
#pragma unroll
        for (int mt = 0; mt < 4; mt++)
#pragma unroll
            for (int nt = 0; nt < 8; nt++)
                mma8(c[mt][nt], a[mt], b[nt]);
    }
}

__device__ __forceinline__ void gemm_main(const float4* Ag, const float4* Bg, int T,
                                          float c[4][8][4], float* As, float* Bs,
                                          int tid, int wm, int wn, int lane) {
    uint4 sa[4], sb[4];
    ldg_stage(Ag, Bg, 0, sa, sb);
    sts_stage(As, Bs, sa, sb, tid);
    __syncthreads();
    for (int t = 0; t < T; t++) {
        const int buf = t & 1;
        if (t + 1 < T) ldg_stage(Ag, Bg, t + 1, sa, sb);
        compute_chunk(As + buf * ACHUNK, Bs + buf * BCHUNK, c, wm, wn, lane);
        if (t + 1 < T) {
            const int nb = buf ^ 1;
            sts_stage(As + nb * ACHUNK, Bs + nb * BCHUNK, sa, sb, tid);
            __syncthreads();
        }
    }
}

// ---------------- kernel: GEMM1  P = exp(xhat @ xhat^T - 1) ----------------
__global__ __launch_bounds__(128, 2) void gemm1_kernel() {
    __shared__ float As[2 * ACHUNK];
    __shared__ float Bs[2 * BCHUNK];
    const int b = blockIdx.z, m0 = blockIdx.y * 128, n0 = blockIdx.x * 128;
    const int tid = threadIdx.x, wid = tid >> 5, lane = tid & 31;
    const int wm = wid >> 1, wn = wid & 1;

    const float* Xb = g_xhat + (size_t)b * SEQ * DIM;
    const float4* Ag = (const float4*)(Xb + (size_t)(m0 + tid) * DIM);
    const float4* Bg = (const float4*)(Xb + (size_t)(n0 + tid) * DIM);

    float c[4][8][4];
#pragma unroll
    for (int i = 0; i < 4; i++)
#pragma unroll
        for (int j = 0; j < 8; j++)
#pragma unroll
            for (int k = 0; k < 4; k++) c[i][j][k] = 0.f;

    gemm_main(Ag, Bg, DIM / CK, c, As, Bs, tid, wm, wn, lane);

    const int row0 = m0 + wm * 64 + (lane >> 2);
    const int col0 = n0 + wn * 64 + (lane & 3) * 2;
#pragma unroll
    for (int mt = 0; mt < 4; mt++) {
#pragma unroll
        for (int nt = 0; nt < 8; nt++) {
            const int r1 = row0 + mt * 16;
            const int cc = col0 + nt * 8;
            float2 w0, w1;
            w0.x = __expf(c[mt][nt][0] - 1.0f);
            w0.y = __expf(c[mt][nt][1] - 1.0f);
            w1.x = __expf(c[mt][nt][2] - 1.0f);
            w1.y = __expf(c[mt][nt][3] - 1.0f);
            *(float2*)&g_P[((size_t)b * SEQ + r1) * SEQ + cc] = w0;
            *(float2*)&g_P[((size_t)b * SEQ + r1 + 8) * SEQ + cc] = w1;
        }
    }
}

// ---------------- kernel: rowsum ----------------
__global__ void rowsum_kernel() {
    int row  = blockIdx.x * 8 + (threadIdx.x >> 5);
    int lane = threadIdx.x & 31;
    const float4* p = (const float4*)(g_P + (size_t)row * SEQ);
    float s = 0.f;
#pragma unroll
    for (int i = 0; i < 16; i++) {
        float4 v = p[i * 32 + lane];
        s += v.x + v.y + v.z + v.w;
    }
#pragma unroll
    for (int m = 16; m; m >>= 1) s += __shfl_xor_sync(0xffffffffu, s, m);
    if (lane == 0) g_rinv[row] = 1.0f / s;
}

// ---------------- kernel: GEMM2  out = (P @ x) * rinv ----------------
__global__ __launch_bounds__(128, 2) void gemm2_kernel(float* __restrict__ out) {
    __shared__ float As[2 * ACHUNK];
    __shared__ float Bs[2 * BCHUNK];
    const int b = blockIdx.z, m0 = blockIdx.y * 128, n0 = blockIdx.x * 128;
    const int tid = threadIdx.x, wid = tid >> 5, lane = tid & 31;
    const int wm = wid >> 1, wn = wid & 1;

    const float4* Ag = (const float4*)(g_P + ((size_t)b * SEQ + m0 + tid) * SEQ);
    const float4* Bg = (const float4*)(g_xT + ((size_t)b * DIM + n0 + tid) * SEQ);

    float c[4][8][4];
#pragma unroll
    for (int i = 0; i < 4; i++)
#pragma unroll
        for (int j = 0; j < 8; j++)
#pragma unroll
            for (int k = 0; k < 4; k++) c[i][j][k] = 0.f;

    gemm_main(Ag, Bg, SEQ / CK, c, As, Bs, tid, wm, wn, lane);

    const int row0 = m0 + wm * 64 + (lane >> 2);
    const int col0 = n0 + wn * 64 + (lane & 3) * 2;
#pragma unroll
    for (int mt = 0; mt < 4; mt++) {
        const int r1 = row0 + mt * 16;
        const float ri0 = g_rinv[b * SEQ + r1];
        const float ri1 = g_rinv[b * SEQ + r1 + 8];
#pragma unroll
        for (int nt = 0; nt < 8; nt++) {
            const int cc = col0 + nt * 8;
            float2 w0, w1;
            w0.x = c[mt][nt][0] * ri0;
            w0.y = c[mt][nt][1] * ri0;
            w1.x = c[mt][nt][2] * ri1;
            w1.y = c[mt][nt][3] * ri1;
            *(float2*)&out[((size_t)b * SEQ + r1) * DIM + cc] = w0;
            *(float2*)&out[((size_t)b * SEQ + r1 + 8) * DIM + cc] = w1;
        }
    }
}

// ---------------- launch ----------------
extern "C" void kernel_launch(void* const* d_in, const int* in_sizes, int n_in,
                              void* d_out, int out_size) {
    const float* x = (const float*)d_in[0];
    float* out = (float*)d_out;

    xhat_kernel<<<BATCH * SEQ / 8, 256>>>(x);
    xT_kernel<<<dim3(SEQ / 32, DIM / 32, BATCH), dim3(32, 8)>>>(x);
    gemm1_kernel<<<dim3(SEQ / 128, SEQ / 128, BATCH), 128>>>();
    rowsum_kernel<<<BATCH * SEQ / 8, 256>>>();
    gemm2_kernel<<<dim3(DIM / 128, SEQ / 128, BATCH), 128>>>(out);
}

// round 6
// speedup vs baseline: 9.8050x; 1.9417x over previous
#include <cuda_runtime.h>
#include <cuda_fp16.h>
#include <cstdint>

// Cosine self-attention via legacy fp16 tensor-core mma.sync m16n8k16
// (sm_80-baseline PTX; tcgen05 is 'a'-gated and unavailable under the
// harness's compute_103 virtual arch).
//   xhat = half(x / |x|)
//   xT   = half(transpose(x)) per batch
//   P    = half(exp(xhat @ xhat^T - 1))   (fp16 mma, f32 accum)
//   rinv = 1 / rowsum(P)                  (f32 accum)
//   out  = (P @ x) * rinv                 (fp16 mma, f32 accum, f32 out)
// cosine <= 1 => fixed softmax shift exp(s-1) cancels in the ratio.

#define BATCH 16
#define SEQ   2048
#define DIM   512
#define CK    32                 // K per chunk = 2 mma k-steps of 16

__device__ __half g_xhat[BATCH * SEQ * DIM];               // 32 MB
__device__ __half g_xT[BATCH * DIM * SEQ];                 // 32 MB
__device__ __half g_P[(size_t)BATCH * SEQ * SEQ];          // 128 MB
__device__ float  g_rinv[BATCH * SEQ];

// ---------------- mma helper ----------------
__device__ __forceinline__ void mma16(float c[4], const uint32_t a[4],
                                      const uint32_t b[2]) {
    asm volatile(
        "mma.sync.aligned.m16n8k16.row.col.f32.f16.f16.f32 "
        "{%0,%1,%2,%3}, {%4,%5,%6,%7}, {%8,%9}, {%0,%1,%2,%3};"
        : "+f"(c[0]), "+f"(c[1]), "+f"(c[2]), "+f"(c[3])
        : "r"(a[0]), "r"(a[1]), "r"(a[2]), "r"(a[3]), "r"(b[0]), "r"(b[1]));
}

// ---------------- kernel: xhat (f32 -> normalized half) ----------------
__global__ void xhat_kernel(const float* __restrict__ x) {
    int row  = blockIdx.x * 8 + (threadIdx.x >> 5);
    int lane = threadIdx.x & 31;
    const float4* xr = (const float4*)x + (size_t)row * (DIM / 4);
    float4 v[4];
    float ss = 0.f;
#pragma unroll
    for (int i = 0; i < 4; i++) {
        v[i] = xr[i * 32 + lane];
        ss += v[i].x * v[i].x + v[i].y * v[i].y + v[i].z * v[i].z + v[i].w * v[i].w;
    }
#pragma unroll
    for (int m = 16; m; m >>= 1) ss += __shfl_xor_sync(0xffffffffu, ss, m);
    float s = 1.0f / sqrtf(ss);
    uint2* o = (uint2*)(g_xhat + (size_t)row * DIM);   // 4 halves per uint2
#pragma unroll
    for (int i = 0; i < 4; i++) {
        __half2 h0 = __floats2half2_rn(v[i].x * s, v[i].y * s);
        __half2 h1 = __floats2half2_rn(v[i].z * s, v[i].w * s);
        uint2 u;
        u.x = *(uint32_t*)&h0;
        u.y = *(uint32_t*)&h1;
        o[i * 32 + lane] = u;
    }
}

// ---------------- kernel: xT (per-batch transpose, f32 -> half) ----------
__global__ void xT_kernel(const float* __restrict__ x) {
    __shared__ float t[32][33];
    const int b = blockIdx.z, s0 = blockIdx.x * 32, d0 = blockIdx.y * 32;
    const int tx = threadIdx.x, ty = threadIdx.y;
#pragma unroll
    for (int i = 0; i < 4; i++)
        t[ty + 8 * i][tx] = x[((size_t)b * SEQ + s0 + ty + 8 * i) * DIM + d0 + tx];
    __syncthreads();
#pragma unroll
    for (int i = 0; i < 4; i++)
        g_xT[((size_t)b * DIM + d0 + ty + 8 * i) * SEQ + s0 + tx] =
            __float2half(t[tx][ty + 8 * i]);
}

// ---------------- GEMM core (128x128 CTA, 4 warps, 64x64 warp tiles) -------
// fp16 fragment-ordered smem (half2 = uint32 units):
//   A: ((kstep*8  + mtile)*4 + reg)*32 + lane      (2*8*4*32 = 2048 u32 = 8KB)
//   B: ((kstep*16 + ntile)*2 + reg)*32 + lane      (2*16*2*32 = 2048 u32 = 8KB)
// STS.128 conflict-free (each 8-lane phase writes 8 consecutive 16B quads);
// fragment LDS.32 lane-stride-1 conflict-free.
#define ACHUNK 2048   // u32 units
#define BCHUNK 2048

__device__ __forceinline__ void ldg_stage(const uint4* Ag, const uint4* Bg,
                                          int t, uint4 sa[4], uint4 sb[4]) {
#pragma unroll
    for (int q = 0; q < 4; q++) {
        sa[q] = Ag[t * 4 + q];
        sb[q] = Bg[t * 4 + q];
    }
}

__device__ __forceinline__ void sts_stage(uint32_t* Abuf, uint32_t* Bbuf,
                                          const uint4 sa[4], const uint4 sb[4],
                                          int tid) {
    // A: row r = tid. mtile = r>>4, rit = r&15.
    //   reg0/2 <- rit<8 (a0/a2), reg1/3 <- rit>=8 (a1/a3); lane4 = (rit&7)*4
    const int mtile = tid >> 4;
    const int r0    = (tid >> 3) & 1;
    const int la4   = (tid & 7) * 4;
    // B: row n = tid. ntile = n>>3; lane4 = (n&7)*4
    const int ntile = tid >> 3;
#pragma unroll
    for (int q = 0; q < 4; q++) {
        const int ks = q >> 1;
        const int regA = (q & 1) * 2 + r0;       // pairs 0-3 -> a0/a1, 4-7 -> a2/a3
        *(uint4*)&Abuf[((ks * 8 + mtile) * 4 + regA) * 32 + la4] = sa[q];
        const int regB = q & 1;                  // pairs 0-3 -> b0, 4-7 -> b1
        *(uint4*)&Bbuf[((ks * 16 + ntile) * 2 + regB) * 32 + la4] = sb[q];
    }
}

__device__ __forceinline__ void compute_chunk(const uint32_t* Abuf,
                                              const uint32_t* Bbuf,
                                              float c[4][8][4], int wm, int wn,
                                              int lane) {
#pragma unroll
    for (int ks = 0; ks < 2; ks++) {
        uint32_t a[4][4], b[8][2];
#pragma unroll
        for (int mt = 0; mt < 4; mt++) {
            const uint32_t* p = Abuf + ((ks * 8 + wm * 4 + mt) * 4) * 32 + lane;
#pragma unroll
            for (int j = 0; j < 4; j++) a[mt][j] = p[j * 32];
        }
#pragma unroll
        for (int nt = 0; nt < 8; nt++) {
            const uint32_t* p = Bbuf + ((ks * 16 + wn * 8 + nt) * 2) * 32 + lane;
#pragma unroll
            for (int j = 0; j < 2; j++) b[nt][j] = p[j * 32];
        }
#pragma unroll
        for (int mt = 0; mt < 4; mt++)
#pragma unroll
            for (int nt = 0; nt < 8; nt++)
                mma16(c[mt][nt], a[mt], b[nt]);
    }
}

__device__ __forceinline__ void gemm_main(const uint4* Ag, const uint4* Bg, int T,
                                          float c[4][8][4], uint32_t* As,
                                          uint32_t* Bs, int tid, int wm, int wn,
                                          int lane) {
    uint4 sa[4], sb[4];
    ldg_stage(Ag, Bg, 0, sa, sb);
    sts_stage(As, Bs, sa, sb, tid);
    __syncthreads();
    for (int t = 0; t < T; t++) {
        const int buf = t & 1;
        if (t + 1 < T) ldg_stage(Ag, Bg, t + 1, sa, sb);
        compute_chunk(As + buf * ACHUNK, Bs + buf * BCHUNK, c, wm, wn, lane);
        if (t + 1 < T) {
            const int nb = buf ^ 1;
            sts_stage(As + nb * ACHUNK, Bs + nb * BCHUNK, sa, sb, tid);
            __syncthreads();
        }
    }
}

// ---------------- kernel: GEMM1  P = half(exp(xhat @ xhat^T - 1)) ----------
__global__ __launch_bounds__(128, 2) void gemm1_kernel() {
    __shared__ uint32_t As[2 * ACHUNK];
    __shared__ uint32_t Bs[2 * BCHUNK];
    const int b = blockIdx.z, m0 = blockIdx.y * 128, n0 = blockIdx.x * 128;
    const int tid = threadIdx.x, wid = tid >> 5, lane = tid & 31;
    const int wm = wid >> 1, wn = wid & 1;

    const __half* Xb = g_xhat + (size_t)b * SEQ * DIM;
    const uint4* Ag = (const uint4*)(Xb + (size_t)(m0 + tid) * DIM);
    const uint4* Bg = (const uint4*)(Xb + (size_t)(n0 + tid) * DIM);

    float c[4][8][4];
#pragma unroll
    for (int i = 0; i < 4; i++)
#pragma unroll
        for (int j = 0; j < 8; j++)
#pragma unroll
            for (int k = 0; k < 4; k++) c[i][j][k] = 0.f;

    gemm_main(Ag, Bg, DIM / CK, c, As, Bs, tid, wm, wn, lane);

    const int row0 = m0 + wm * 64 + (lane >> 2);
    const int col0 = n0 + wn * 64 + (lane & 3) * 2;
#pragma unroll
    for (int mt = 0; mt < 4; mt++) {
#pragma unroll
        for (int nt = 0; nt < 8; nt++) {
            const int r1 = row0 + mt * 16;
            const int cc = col0 + nt * 8;
            __half2 h0 = __floats2half2_rn(__expf(c[mt][nt][0] - 1.0f),
                                           __expf(c[mt][nt][1] - 1.0f));
            __half2 h1 = __floats2half2_rn(__expf(c[mt][nt][2] - 1.0f),
                                           __expf(c[mt][nt][3] - 1.0f));
            *(__half2*)&g_P[((size_t)b * SEQ + r1) * SEQ + cc] = h0;
            *(__half2*)&g_P[((size_t)b * SEQ + r1 + 8) * SEQ + cc] = h1;
        }
    }
}

// ---------------- kernel: rowsum (half P, f32 accum) ----------------
__global__ void rowsum_kernel() {
    int row  = blockIdx.x * 8 + (threadIdx.x >> 5);
    int lane = threadIdx.x & 31;
    const uint4* p = (const uint4*)(g_P + (size_t)row * SEQ);  // 8 halves per uint4
    float s = 0.f;
#pragma unroll
    for (int i = 0; i < 8; i++) {
        uint4 v = p[i * 32 + lane];
        float2 f;
        f = __half22float2(*(__half2*)&v.x); s += f.x + f.y;
        f = __half22float2(*(__half2*)&v.y); s += f.x + f.y;
        f = __half22float2(*(__half2*)&v.z); s += f.x + f.y;
        f = __half22float2(*(__half2*)&v.w); s += f.x + f.y;
    }
#pragma unroll
    for (int m = 16; m; m >>= 1) s += __shfl_xor_sync(0xffffffffu, s, m);
    if (lane == 0) g_rinv[row] = 1.0f / s;
}

// ---------------- kernel: GEMM2  out = (P @ x) * rinv ----------------
__global__ __launch_bounds__(128, 2) void gemm2_kernel(float* __restrict__ out) {
    __shared__ uint32_t As[2 * ACHUNK];
    __shared__ uint32_t Bs[2 * BCHUNK];
    const int b = blockIdx.z, m0 = blockIdx.y * 128, n0 = blockIdx.x * 128;
    const int tid = threadIdx.x, wid = tid >> 5, lane = tid & 31;
    const int wm = wid >> 1, wn = wid & 1;

    const uint4* Ag = (const uint4*)(g_P + ((size_t)b * SEQ + m0 + tid) * SEQ);
    const uint4* Bg = (const uint4*)(g_xT + ((size_t)b * DIM + n0 + tid) * SEQ);

    float c[4][8][4];
#pragma unroll
    for (int i = 0; i < 4; i++)
#pragma unroll
        for (int j = 0; j < 8; j++)
#pragma unroll
            for (int k = 0; k < 4; k++) c[i][j][k] = 0.f;

    gemm_main(Ag, Bg, SEQ / CK, c, As, Bs, tid, wm, wn, lane);

    const int row0 = m0 + wm * 64 + (lane >> 2);
    const int col0 = n0 + wn * 64 + (lane & 3) * 2;
#pragma unroll
    for (int mt = 0; mt < 4; mt++) {
        const int r1 = row0 + mt * 16;
        const float ri0 = g_rinv[b * SEQ + r1];
        const float ri1 = g_rinv[b * SEQ + r1 + 8];
#pragma unroll
        for (int nt = 0; nt < 8; nt++) {
            const int cc = col0 + nt * 8;
            float2 w0, w1;
            w0.x = c[mt][nt][0] * ri0;
            w0.y = c[mt][nt][1] * ri0;
            w1.x = c[mt][nt][2] * ri1;
            w1.y = c[mt][nt][3] * ri1;
            *(float2*)&out[((size_t)b * SEQ + r1) * DIM + cc] = w0;
            *(float2*)&out[((size_t)b * SEQ + r1 + 8) * DIM + cc] = w1;
        }
    }
}

// ---------------- launch ----------------
extern "C" void kernel_launch(void* const* d_in, const int* in_sizes, int n_in,
                              void* d_out, int out_size) {
    const float* x = (const float*)d_in[0];
    float* out = (float*)d_out;

    xhat_kernel<<<BATCH * SEQ / 8, 256>>>(x);
    xT_kernel<<<dim3(SEQ / 32, DIM / 32, BATCH), dim3(32, 8)>>>(x);
    gemm1_kernel<<<dim3(SEQ / 128, SEQ / 128, BATCH), 128>>>();
    rowsum_kernel<<<BATCH * SEQ / 8, 256>>>();
    gemm2_kernel<<<dim3(DIM / 128, SEQ / 128, BATCH), 128>>>(out);
}

// round 8
// speedup vs baseline: 11.9776x; 1.2216x over previous
#include <cuda_runtime.h>
#include <cuda_fp16.h>
#include <cstdint>

// Cosine self-attention via legacy fp16 tensor-core mma.sync m16n8k16.
// P = exp(xhat xhat^T - 1) is SYMMETRIC: compute only upper-triangular
// 128x128 tile-pairs (136 of 256 per batch) and write the mirror block via
// in-register movmatrix transpose.
//   xhat = half(x / |x|)
//   xT   = half(transpose(x)) per batch
//   P    = half(exp(xhat @ xhat^T - 1))   (fp16 mma, f32 accum, symmetric)
//   rinv = 1 / rowsum(P)
//   out  = (P @ x) * rinv

#define BATCH 16
#define SEQ   2048
#define DIM   512
#define CK    32                 // K per chunk = 2 mma k-steps of 16
#define NTILE 16                 // 2048/128 tile-blocks per side
#define NPAIR 136                // NTILE*(NTILE+1)/2

__device__ __half g_xhat[BATCH * SEQ * DIM];               // 32 MB
__device__ __half g_xT[BATCH * DIM * SEQ];                 // 32 MB
__device__ __half g_P[(size_t)BATCH * SEQ * SEQ];          // 128 MB
__device__ float  g_rinv[BATCH * SEQ];

// ---------------- mma / movmatrix helpers ----------------
__device__ __forceinline__ void mma16(float c[4], const uint32_t a[4],
                                      const uint32_t b[2]) {
    asm volatile(
        "mma.sync.aligned.m16n8k16.row.col.f32.f16.f16.f32 "
        "{%0,%1,%2,%3}, {%4,%5,%6,%7}, {%8,%9}, {%0,%1,%2,%3};"
        : "+f"(c[0]), "+f"(c[1]), "+f"(c[2]), "+f"(c[3])
        : "r"(a[0]), "r"(a[1]), "r"(a[2]), "r"(a[3]), "r"(b[0]), "r"(b[1]));
}
__device__ __forceinline__ uint32_t movmat(uint32_t a) {
    uint32_t d;
    asm("movmatrix.sync.aligned.m8n8.trans.b16 %0, %1;" : "=r"(d) : "r"(a));
    return d;
}

// ---------------- kernel: xhat (f32 -> normalized half) ----------------
__global__ void xhat_kernel(const float* __restrict__ x) {
    int row  = blockIdx.x * 8 + (threadIdx.x >> 5);
    int lane = threadIdx.x & 31;
    const float4* xr = (const float4*)x + (size_t)row * (DIM / 4);
    float4 v[4];
    float ss = 0.f;
#pragma unroll
    for (int i = 0; i < 4; i++) {
        v[i] = xr[i * 32 + lane];
        ss += v[i].x * v[i].x + v[i].y * v[i].y + v[i].z * v[i].z + v[i].w * v[i].w;
    }
#pragma unroll
    for (int m = 16; m; m >>= 1) ss += __shfl_xor_sync(0xffffffffu, ss, m);
    float s = 1.0f / sqrtf(ss);
    uint2* o = (uint2*)(g_xhat + (size_t)row * DIM);
#pragma unroll
    for (int i = 0; i < 4; i++) {
        __half2 h0 = __floats2half2_rn(v[i].x * s, v[i].y * s);
        __half2 h1 = __floats2half2_rn(v[i].z * s, v[i].w * s);
        uint2 u;
        u.x = *(uint32_t*)&h0;
        u.y = *(uint32_t*)&h1;
        o[i * 32 + lane] = u;
    }
}

// ---------------- kernel: xT (per-batch transpose, f32 -> half) ----------
__global__ void xT_kernel(const float* __restrict__ x) {
    __shared__ float t[32][33];
    const int b = blockIdx.z, s0 = blockIdx.x * 32, d0 = blockIdx.y * 32;
    const int tx = threadIdx.x, ty = threadIdx.y;
#pragma unroll
    for (int i = 0; i < 4; i++)
        t[ty + 8 * i][tx] = x[((size_t)b * SEQ + s0 + ty + 8 * i) * DIM + d0 + tx];
    __syncthreads();
#pragma unroll
    for (int i = 0; i < 4; i++)
        g_xT[((size_t)b * DIM + d0 + ty + 8 * i) * SEQ + s0 + tx] =
            __float2half(t[tx][ty + 8 * i]);
}

// ---------------- GEMM core (128x128 CTA, 4 warps, 64x64 warp tiles) -------
#define ACHUNK 2048   // u32 units
#define BCHUNK 2048

__device__ __forceinline__ void ldg_stage(const uint4* Ag, const uint4* Bg,
                                          int t, uint4 sa[4], uint4 sb[4]) {
#pragma unroll
    for (int q = 0; q < 4; q++) {
        sa[q] = Ag[t * 4 + q];
        sb[q] = Bg[t * 4 + q];
    }
}

__device__ __forceinline__ void sts_stage(uint32_t* Abuf, uint32_t* Bbuf,
                                          const uint4 sa[4], const uint4 sb[4],
                                          int tid) {
    const int mtile = tid >> 4;
    const int r0    = (tid >> 3) & 1;
    const int la4   = (tid & 7) * 4;
    const int ntile = tid >> 3;
#pragma unroll
    for (int q = 0; q < 4; q++) {
        const int ks = q >> 1;
        const int regA = (q & 1) * 2 + r0;
        *(uint4*)&Abuf[((ks * 8 + mtile) * 4 + regA) * 32 + la4] = sa[q];
        const int regB = q & 1;
        *(uint4*)&Bbuf[((ks * 16 + ntile) * 2 + regB) * 32 + la4] = sb[q];
    }
}

__device__ __forceinline__ void compute_chunk(const uint32_t* Abuf,
                                              const uint32_t* Bbuf,
                                              float c[4][8][4], int wm, int wn,
                                              int lane) {
#pragma unroll
    for (int ks = 0; ks < 2; ks++) {
        uint32_t a[4][4], b[8][2];
#pragma unroll
        for (int mt = 0; mt < 4; mt++) {
            const uint32_t* p = Abuf + ((ks * 8 + wm * 4 + mt) * 4) * 32 + lane;
#pragma unroll
            for (int j = 0; j < 4; j++) a[mt][j] = p[j * 32];
        }
#pragma unroll
        for (int nt = 0; nt < 8; nt++) {
            const uint32_t* p = Bbuf + ((ks * 16 + wn * 8 + nt) * 2) * 32 + lane;
#pragma unroll
            for (int j = 0; j < 2; j++) b[nt][j] = p[j * 32];
        }
#pragma unroll
        for (int mt = 0; mt < 4; mt++)
#pragma unroll
            for (int nt = 0; nt < 8; nt++)
                mma16(c[mt][nt], a[mt], b[nt]);
    }
}

__device__ __forceinline__ void gemm_main(const uint4* Ag, const uint4* Bg, int T,
                                          float c[4][8][4], uint32_t* As,
                                          uint32_t* Bs, int tid, int wm, int wn,
                                          int lane) {
    uint4 sa[4], sb[4];
    ldg_stage(Ag, Bg, 0, sa, sb);
    sts_stage(As, Bs, sa, sb, tid);
    __syncthreads();
    for (int t = 0; t < T; t++) {
        const int buf = t & 1;
        if (t + 1 < T) ldg_stage(Ag, Bg, t + 1, sa, sb);
        compute_chunk(As + buf * ACHUNK, Bs + buf * BCHUNK, c, wm, wn, lane);
        if (t + 1 < T) {
            const int nb = buf ^ 1;
            sts_stage(As + nb * ACHUNK, Bs + nb * BCHUNK, sa, sb, tid);
            __syncthreads();
        }
    }
}

// ------- kernel: GEMM1 (symmetric)  P = half(exp(xhat xhat^T - 1)) ---------
// blockIdx.x = upper-tri tile-pair index (i <= j); writes block (i,j) and,
// when i != j, block (j,i) via movmatrix register transpose.
__global__ __launch_bounds__(128, 2) void gemm1_kernel() {
    __shared__ uint32_t As[2 * ACHUNK];
    __shared__ uint32_t Bs[2 * BCHUNK];
    const int b = blockIdx.z;
    // closed-form decode: pair index -> (ti, tj), ti <= tj
    // idx = ti*NTILE - ti*(ti-1)/2 + (tj - ti)
    const int idx = blockIdx.x;
    int ti = (int)(NTILE + 0.5f -
                   sqrtf((NTILE + 0.5f) * (NTILE + 0.5f) - 2.0f * idx - 0.25f));
    // guard against fp rounding at segment boundaries
    while (ti * NTILE - ti * (ti - 1) / 2 > idx) ti--;
    while ((ti + 1) * NTILE - (ti + 1) * ti / 2 <= idx) ti++;
    const int tj = ti + (idx - (ti * NTILE - ti * (ti - 1) / 2));
    const int m0 = ti * 128, n0 = tj * 128;

    const int tid = threadIdx.x, wid = tid >> 5, lane = tid & 31;
    const int wm = wid >> 1, wn = wid & 1;

    const __half* Xb = g_xhat + (size_t)b * SEQ * DIM;
    const uint4* Ag = (const uint4*)(Xb + (size_t)(m0 + tid) * DIM);
    const uint4* Bg = (const uint4*)(Xb + (size_t)(n0 + tid) * DIM);

    float c[4][8][4];
#pragma unroll
    for (int i = 0; i < 4; i++)
#pragma unroll
        for (int j = 0; j < 8; j++)
#pragma unroll
            for (int k = 0; k < 4; k++) c[i][j][k] = 0.f;

    gemm_main(Ag, Bg, DIM / CK, c, As, Bs, tid, wm, wn, lane);

    const int row0 = m0 + wm * 64 + (lane >> 2);
    const int col0 = n0 + wn * 64 + (lane & 3) * 2;
    const bool mirror = (ti != tj);
#pragma unroll
    for (int mt = 0; mt < 4; mt++) {
#pragma unroll
        for (int nt = 0; nt < 8; nt++) {
            const int r1 = row0 + mt * 16;
            const int cc = col0 + nt * 8;
            __half2 h0 = __floats2half2_rn(__expf(c[mt][nt][0] - 1.0f),
                                           __expf(c[mt][nt][1] - 1.0f));
            __half2 h1 = __floats2half2_rn(__expf(c[mt][nt][2] - 1.0f),
                                           __expf(c[mt][nt][3] - 1.0f));
            *(__half2*)&g_P[((size_t)b * SEQ + r1) * SEQ + cc] = h0;
            *(__half2*)&g_P[((size_t)b * SEQ + r1 + 8) * SEQ + cc] = h1;
            if (mirror) {
                // 8x8 sub-blocks transpose in-register; mirror block (tj,ti)
                uint32_t t0 = movmat(*(uint32_t*)&h0);
                uint32_t t1 = movmat(*(uint32_t*)&h1);
                const int rm = n0 + wn * 64 + nt * 8 + (lane >> 2);
                const int cm = m0 + wm * 64 + mt * 16 + (lane & 3) * 2;
                *(uint32_t*)&g_P[((size_t)b * SEQ + rm) * SEQ + cm] = t0;
                *(uint32_t*)&g_P[((size_t)b * SEQ + rm) * SEQ + cm + 8] = t1;
            }
        }
    }
}

// ---------------- kernel: rowsum (half P, f32 accum) ----------------
__global__ void rowsum_kernel() {
    int row  = blockIdx.x * 8 + (threadIdx.x >> 5);
    int lane = threadIdx.x & 31;
    const uint4* p = (const uint4*)(g_P + (size_t)row * SEQ);
    float s = 0.f;
#pragma unroll
    for (int i = 0; i < 8; i++) {
        uint4 v = p[i * 32 + lane];
        float2 f;
        f = __half22float2(*(__half2*)&v.x); s += f.x + f.y;
        f = __half22float2(*(__half2*)&v.y); s += f.x + f.y;
        f = __half22float2(*(__half2*)&v.z); s += f.x + f.y;
        f = __half22float2(*(__half2*)&v.w); s += f.x + f.y;
    }
#pragma unroll
    for (int m = 16; m; m >>= 1) s += __shfl_xor_sync(0xffffffffu, s, m);
    if (lane == 0) g_rinv[row] = 1.0f / s;
}

// ---------------- kernel: GEMM2  out = (P @ x) * rinv ----------------
__global__ __launch_bounds__(128, 2) void gemm2_kernel(float* __restrict__ out) {
    __shared__ uint32_t As[2 * ACHUNK];
    __shared__ uint32_t Bs[2 * BCHUNK];
    const int b = blockIdx.z, m0 = blockIdx.y * 128, n0 = blockIdx.x * 128;
    const int tid = threadIdx.x, wid = tid >> 5, lane = tid & 31;
    const int wm = wid >> 1, wn = wid & 1;

    const uint4* Ag = (const uint4*)(g_P + ((size_t)b * SEQ + m0 + tid) * SEQ);
    const uint4* Bg = (const uint4*)(g_xT + ((size_t)b * DIM + n0 + tid) * SEQ);

    float c[4][8][4];
#pragma unroll
    for (int i = 0; i < 4; i++)
#pragma unroll
        for (int j = 0; j < 8; j++)
#pragma unroll
            for (int k = 0; k < 4; k++) c[i][j][k] = 0.f;

    gemm_main(Ag, Bg, SEQ / CK, c, As, Bs, tid, wm, wn, lane);

    const int row0 = m0 + wm * 64 + (lane >> 2);
    const int col0 = n0 + wn * 64 + (lane & 3) * 2;
#pragma unroll
    for (int mt = 0; mt < 4; mt++) {
        const int r1 = row0 + mt * 16;
        const float ri0 = g_rinv[b * SEQ + r1];
        const float ri1 = g_rinv[b * SEQ + r1 + 8];
#pragma unroll
        for (int nt = 0; nt < 8; nt++) {
            const int cc = col0 + nt * 8;
            float2 w0, w1;
            w0.x = c[mt][nt][0] * ri0;
            w0.y = c[mt][nt][1] * ri0;
            w1.x = c[mt][nt][2] * ri1;
            w1.y = c[mt][nt][3] * ri1;
            *(float2*)&out[((size_t)b * SEQ + r1) * DIM + cc] = w0;
            *(float2*)&out[((size_t)b * SEQ + r1 + 8) * DIM + cc] = w1;
        }
    }
}

// ---------------- launch ----------------
extern "C" void kernel_launch(void* const* d_in, const int* in_sizes, int n_in,
                              void* d_out, int out_size) {
    const float* x = (const float*)d_in[0];
    float* out = (float*)d_out;

    xhat_kernel<<<BATCH * SEQ / 8, 256>>>(x);
    xT_kernel<<<dim3(SEQ / 32, DIM / 32, BATCH), dim3(32, 8)>>>(x);
    gemm1_kernel<<<dim3(NPAIR, 1, BATCH), 128>>>();
    rowsum_kernel<<<BATCH * SEQ / 8, 256>>>();
    gemm2_kernel<<<dim3(DIM / 128, SEQ / 128, BATCH), 128>>>(out);
}

// round 9
// speedup vs baseline: 13.7612x; 1.1489x over previous
#include <cuda_runtime.h>
#include <cuda_fp16.h>
#include <cstdint>

// Cosine self-attention, fp16 mma.sync m16n8k16, symmetric GEMM1,
// cp.async 3-stage pipelined mainloops, rowsum fused into GEMM2
// (row sums recovered from GEMM2's own A fragments — no extra traffic).
//   xhat = half(x / |x|)
//   xT   = half(transpose(x)) per batch
//   P    = half(exp(xhat @ xhat^T - 1))   (symmetric: 136/256 tiles + mirror)
//   out  = (P @ x) / rowsum(P)            (rowsum computed in-kernel)

#define BATCH 16
#define SEQ   2048
#define DIM   512
#define CK    32
#define NTILE 16
#define NPAIR 136

__device__ __half g_xhat[BATCH * SEQ * DIM];               // 32 MB
__device__ __half g_xT[BATCH * DIM * SEQ];                 // 32 MB
__device__ __half g_P[(size_t)BATCH * SEQ * SEQ];          // 128 MB

// ---------------- ptx helpers ----------------
__device__ __forceinline__ void mma16(float c[4], const uint32_t a[4],
                                      const uint32_t b[2]) {
    asm volatile(
        "mma.sync.aligned.m16n8k16.row.col.f32.f16.f16.f32 "
        "{%0,%1,%2,%3}, {%4,%5,%6,%7}, {%8,%9}, {%0,%1,%2,%3};"
        : "+f"(c[0]), "+f"(c[1]), "+f"(c[2]), "+f"(c[3])
        : "r"(a[0]), "r"(a[1]), "r"(a[2]), "r"(a[3]), "r"(b[0]), "r"(b[1]));
}
__device__ __forceinline__ uint32_t movmat(uint32_t a) {
    uint32_t d;
    asm("movmatrix.sync.aligned.m8n8.trans.b16 %0, %1;" : "=r"(d) : "r"(a));
    return d;
}
__device__ __forceinline__ void cp16(uint32_t dst, const void* src) {
    asm volatile("cp.async.cg.shared.global [%0], [%1], 16;"
                 :: "r"(dst), "l"(src) : "memory");
}
__device__ __forceinline__ void cp_commit() {
    asm volatile("cp.async.commit_group;" ::: "memory");
}

// ---------------- kernel: xhat (f32 -> normalized half) ----------------
__global__ void xhat_kernel(const float* __restrict__ x) {
    int row  = blockIdx.x * 8 + (threadIdx.x >> 5);
    int lane = threadIdx.x & 31;
    const float4* xr = (const float4*)x + (size_t)row * (DIM / 4);
    float4 v[4];
    float ss = 0.f;
#pragma unroll
    for (int i = 0; i < 4; i++) {
        v[i] = xr[i * 32 + lane];
        ss += v[i].x * v[i].x + v[i].y * v[i].y + v[i].z * v[i].z + v[i].w * v[i].w;
    }
#pragma unroll
    for (int m = 16; m; m >>= 1) ss += __shfl_xor_sync(0xffffffffu, ss, m);
    float s = 1.0f / sqrtf(ss);
    uint2* o = (uint2*)(g_xhat + (size_t)row * DIM);
#pragma unroll
    for (int i = 0; i < 4; i++) {
        __half2 h0 = __floats2half2_rn(v[i].x * s, v[i].y * s);
        __half2 h1 = __floats2half2_rn(v[i].z * s, v[i].w * s);
        uint2 u;
        u.x = *(uint32_t*)&h0;
        u.y = *(uint32_t*)&h1;
        o[i * 32 + lane] = u;
    }
}

// ---------------- kernel: xT (per-batch transpose, f32 -> half) ----------
__global__ void xT_kernel(const float* __restrict__ x) {
    __shared__ float t[32][33];
    const int b = blockIdx.z, s0 = blockIdx.x * 32, d0 = blockIdx.y * 32;
    const int tx = threadIdx.x, ty = threadIdx.y;
#pragma unroll
    for (int i = 0; i < 4; i++)
        t[ty + 8 * i][tx] = x[((size_t)b * SEQ + s0 + ty + 8 * i) * DIM + d0 + tx];
    __syncthreads();
#pragma unroll
    for (int i = 0; i < 4; i++)
        g_xT[((size_t)b * DIM + d0 + ty + 8 * i) * SEQ + s0 + tx] =
            __float2half(t[tx][ty + 8 * i]);
}

// ------- GEMM core: 128x128 CTA, 4 warps (64x64 tiles), cp.async 3-stage ----
#define CHUNK_U32 2048              // per-stage per-operand (8 KB)
#define STAGE_B   8192              // bytes per stage per operand

template <bool SUMROWS>
__device__ __forceinline__ void compute_chunk(const uint32_t* Abuf,
                                              const uint32_t* Bbuf,
                                              float c[4][8][4], int wm, int wn,
                                              int lane, float* sumA) {
#pragma unroll
    for (int ks = 0; ks < 2; ks++) {
        uint32_t a[4][4], b[8][2];
#pragma unroll
        for (int mt = 0; mt < 4; mt++) {
            const uint32_t* p = Abuf + ((ks * 8 + wm * 4 + mt) * 4) * 32 + lane;
#pragma unroll
            for (int j = 0; j < 4; j++) a[mt][j] = p[j * 32];
        }
#pragma unroll
        for (int nt = 0; nt < 8; nt++) {
            const uint32_t* p = Bbuf + ((ks * 16 + wn * 8 + nt) * 2) * 32 + lane;
#pragma unroll
            for (int j = 0; j < 2; j++) b[nt][j] = p[j * 32];
        }
        if (SUMROWS && wn == 0) {
            // A-fragment rows: a0/a2 -> row r, a1/a3 -> row r+8; lanes sharing
            // l>>2 cover all 16 k-cols of this ks step across l&3.
#pragma unroll
            for (int mt = 0; mt < 4; mt++) {
                float2 f0 = __half22float2(*(__half2*)&a[mt][0]);
                float2 f2 = __half22float2(*(__half2*)&a[mt][2]);
                sumA[mt * 2] += (f0.x + f0.y) + (f2.x + f2.y);
                float2 f1 = __half22float2(*(__half2*)&a[mt][1]);
                float2 f3 = __half22float2(*(__half2*)&a[mt][3]);
                sumA[mt * 2 + 1] += (f1.x + f1.y) + (f3.x + f3.y);
            }
        }
#pragma unroll
        for (int mt = 0; mt < 4; mt++)
#pragma unroll
            for (int nt = 0; nt < 8; nt++)
                mma16(c[mt][nt], a[mt], b[nt]);
    }
}

template <bool SUMROWS>
__device__ __forceinline__ void gemm_main(const uint4* Ag, const uint4* Bg, int T,
                                          float c[4][8][4], uint32_t* As,
                                          uint32_t* Bs, int tid, int wm, int wn,
                                          int lane, float* sumA) {
    const int mtile = tid >> 4;
    const int r0    = (tid >> 3) & 1;
    const int la4   = (tid & 7) * 4;
    const int ntile = tid >> 3;
    uint32_t aoff[4], boff[4];       // byte offsets within one stage
#pragma unroll
    for (int q = 0; q < 4; q++) {
        const int ks = q >> 1;
        const int regA = (q & 1) * 2 + r0;
        aoff[q] = (((ks * 8 + mtile) * 4 + regA) * 32 + la4) * 4;
        const int regB = q & 1;
        boff[q] = (((ks * 16 + ntile) * 2 + regB) * 32 + la4) * 4;
    }
    const uint32_t aS = (uint32_t)__cvta_generic_to_shared(As);
    const uint32_t bS = (uint32_t)__cvta_generic_to_shared(Bs);

    auto issue = [&](int t) {
        const uint32_t s = (uint32_t)(t % 3) * STAGE_B;
#pragma unroll
        for (int q = 0; q < 4; q++) cp16(aS + s + aoff[q], &Ag[t * 4 + q]);
#pragma unroll
        for (int q = 0; q < 4; q++) cp16(bS + s + boff[q], &Bg[t * 4 + q]);
        cp_commit();
    };

    issue(0);
    if (T > 1) issue(1);
    for (int t = 0; t < T; t++) {
        if (t + 1 < T)
            asm volatile("cp.async.wait_group 1;" ::: "memory");
        else
            asm volatile("cp.async.wait_group 0;" ::: "memory");
        __syncthreads();
        if (t + 2 < T) issue(t + 2);
        const int s = t % 3;
        compute_chunk<SUMROWS>(As + s * CHUNK_U32, Bs + s * CHUNK_U32, c, wm, wn,
                               lane, sumA);
    }
}

// ------- kernel: GEMM1 (symmetric)  P = half(exp(xhat xhat^T - 1)) ---------
__global__ __launch_bounds__(128, 2) void gemm1_kernel() {
    __shared__ __align__(16) uint32_t As[3 * CHUNK_U32];
    __shared__ __align__(16) uint32_t Bs[3 * CHUNK_U32];
    const int b = blockIdx.z;
    const int idx = blockIdx.x;
    int ti = (int)(NTILE + 0.5f -
                   sqrtf((NTILE + 0.5f) * (NTILE + 0.5f) - 2.0f * idx - 0.25f));
    while (ti * NTILE - ti * (ti - 1) / 2 > idx) ti--;
    while ((ti + 1) * NTILE - (ti + 1) * ti / 2 <= idx) ti++;
    const int tj = ti + (idx - (ti * NTILE - ti * (ti - 1) / 2));
    const int m0 = ti * 128, n0 = tj * 128;

    const int tid = threadIdx.x, wid = tid >> 5, lane = tid & 31;
    const int wm = wid >> 1, wn = wid & 1;

    const __half* Xb = g_xhat + (size_t)b * SEQ * DIM;
    const uint4* Ag = (const uint4*)(Xb + (size_t)(m0 + tid) * DIM);
    const uint4* Bg = (const uint4*)(Xb + (size_t)(n0 + tid) * DIM);

    float c[4][8][4];
#pragma unroll
    for (int i = 0; i < 4; i++)
#pragma unroll
        for (int j = 0; j < 8; j++)
#pragma unroll
            for (int k = 0; k < 4; k++) c[i][j][k] = 0.f;
    float dummy[8];

    gemm_main<false>(Ag, Bg, DIM / CK, c, As, Bs, tid, wm, wn, lane, dummy);

    const int row0 = m0 + wm * 64 + (lane >> 2);
    const int col0 = n0 + wn * 64 + (lane & 3) * 2;
    const bool mirror = (ti != tj);
#pragma unroll
    for (int mt = 0; mt < 4; mt++) {
#pragma unroll
        for (int nt = 0; nt < 8; nt++) {
            const int r1 = row0 + mt * 16;
            const int cc = col0 + nt * 8;
            __half2 h0 = __floats2half2_rn(__expf(c[mt][nt][0] - 1.0f),
                                           __expf(c[mt][nt][1] - 1.0f));
            __half2 h1 = __floats2half2_rn(__expf(c[mt][nt][2] - 1.0f),
                                           __expf(c[mt][nt][3] - 1.0f));
            *(__half2*)&g_P[((size_t)b * SEQ + r1) * SEQ + cc] = h0;
            *(__half2*)&g_P[((size_t)b * SEQ + r1 + 8) * SEQ + cc] = h1;
            if (mirror) {
                uint32_t t0 = movmat(*(uint32_t*)&h0);
                uint32_t t1 = movmat(*(uint32_t*)&h1);
                const int rm = n0 + wn * 64 + nt * 8 + (lane >> 2);
                const int cm = m0 + wm * 64 + mt * 16 + (lane & 3) * 2;
                *(uint32_t*)&g_P[((size_t)b * SEQ + rm) * SEQ + cm] = t0;
                *(uint32_t*)&g_P[((size_t)b * SEQ + rm) * SEQ + cm + 8] = t1;
            }
        }
    }
}

// ------- kernel: GEMM2  out = (P @ x) / rowsum(P), rowsum in-kernel --------
__global__ __launch_bounds__(128, 2) void gemm2_kernel(float* __restrict__ out) {
    __shared__ __align__(16) uint32_t As[3 * CHUNK_U32];
    __shared__ __align__(16) uint32_t Bs[3 * CHUNK_U32];
    const int b = blockIdx.z, m0 = blockIdx.y * 128, n0 = blockIdx.x * 128;
    const int tid = threadIdx.x, wid = tid >> 5, lane = tid & 31;
    const int wm = wid >> 1, wn = wid & 1;

    const uint4* Ag = (const uint4*)(g_P + ((size_t)b * SEQ + m0 + tid) * SEQ);
    const uint4* Bg = (const uint4*)(g_xT + ((size_t)b * DIM + n0 + tid) * SEQ);

    float c[4][8][4];
#pragma unroll
    for (int i = 0; i < 4; i++)
#pragma unroll
        for (int j = 0; j < 8; j++)
#pragma unroll
            for (int k = 0; k < 4; k++) c[i][j][k] = 0.f;
    float sumA[8];
#pragma unroll
    for (int i = 0; i < 8; i++) sumA[i] = 0.f;

    gemm_main<true>(Ag, Bg, SEQ / CK, c, As, Bs, tid, wm, wn, lane, sumA);

    // reduce row sums across the 4 lanes sharing each row (lane&3 varies)
#pragma unroll
    for (int i = 0; i < 8; i++) {
        sumA[i] += __shfl_xor_sync(0xffffffffu, sumA[i], 1);
        sumA[i] += __shfl_xor_sync(0xffffffffu, sumA[i], 2);
    }
    __syncthreads();                 // mainloop smem dead; reuse As as f32 sums
    float* rs = (float*)As;
    if (wn == 0 && (lane & 3) == 0) {
#pragma unroll
        for (int mt = 0; mt < 4; mt++) {
            rs[wm * 64 + mt * 16 + (lane >> 2)]     = sumA[mt * 2];
            rs[wm * 64 + mt * 16 + 8 + (lane >> 2)] = sumA[mt * 2 + 1];
        }
    }
    __syncthreads();

    const int row0 = m0 + wm * 64 + (lane >> 2);
    const int col0 = n0 + wn * 64 + (lane & 3) * 2;
#pragma unroll
    for (int mt = 0; mt < 4; mt++) {
        const int lr = wm * 64 + mt * 16 + (lane >> 2);
        const float ri0 = 1.0f / rs[lr];
        const float ri1 = 1.0f / rs[lr + 8];
        const int r1 = row0 + mt * 16;
#pragma unroll
        for (int nt = 0; nt < 8; nt++) {
            const int cc = col0 + nt * 8;
            float2 w0, w1;
            w0.x = c[mt][nt][0] * ri0;
            w0.y = c[mt][nt][1] * ri0;
            w1.x = c[mt][nt][2] * ri1;
            w1.y = c[mt][nt][3] * ri1;
            *(float2*)&out[((size_t)b * SEQ + r1) * DIM + cc] = w0;
            *(float2*)&out[((size_t)b * SEQ + r1 + 8) * DIM + cc] = w1;
        }
    }
}

// ---------------- launch ----------------
extern "C" void kernel_launch(void* const* d_in, const int* in_sizes, int n_in,
                              void* d_out, int out_size) {
    const float* x = (const float*)d_in[0];
    float* out = (float*)d_out;

    xhat_kernel<<<BATCH * SEQ / 8, 256>>>(x);
    xT_kernel<<<dim3(SEQ / 32, DIM / 32, BATCH), dim3(32, 8)>>>(x);
    gemm1_kernel<<<dim3(NPAIR, 1, BATCH), 128>>>();
    gemm2_kernel<<<dim3(DIM / 128, SEQ / 128, BATCH), 128>>>(out);
}